// round 2
// baseline (speedup 1.0000x reference)
#include <cuda_runtime.h>
#include <cuda_bf16.h>
#include <cstdint>

// Problem constants (fixed by the reference)
#define NT      131072
#define HID     2048
#define NRANKS  8
#define NEXP    16
#define NSEG    128            // NRANKS * NEXP
#define VEC     (HID / 4)      // 512 float4 per row
#define NBLK    1184           // 148 SMs * 8 resident blocks

// Scratch (no device allocation allowed -> __device__ globals)
__device__ int g_base_in[NSEG];     // input-row base for each output segment
__device__ int g_out_off[NSEG + 1]; // exclusive cumsum of output segment sizes

// -------------------------------------------------------------------------
// Setup: compute segment offset tables + expert_token_num tail of output.
// counts layout: counts[r * NEXP + e], rank-major (input order).
// Output segment order: p = e * NRANKS + r (expert-major, rank-minor).
// -------------------------------------------------------------------------
__global__ void moe_setup_kernel(const int* __restrict__ counts,
                                 float* __restrict__ out,
                                 long long out_elems) {
    __shared__ int sc[NSEG];
    if (threadIdx.x < NSEG) sc[threadIdx.x] = counts[threadIdx.x];
    __syncthreads();

    if (threadIdx.x == 0) {
        int in_off[NSEG + 1];
        in_off[0] = 0;
        #pragma unroll 4
        for (int s = 0; s < NSEG; s++) in_off[s + 1] = in_off[s] + sc[s];

        int acc = 0;
        for (int p = 0; p < NSEG; p++) {
            int e = p >> 3;          // p / NRANKS
            int r = p & 7;           // p % NRANKS
            int inseg = r * NEXP + e;
            g_base_in[p] = in_off[inseg];
            g_out_off[p] = acc;
            acc += sc[inseg];
        }
        g_out_off[NSEG] = acc;       // == NT
    }
    __syncthreads();

    if (threadIdx.x < NEXP) {
        int e = threadIdx.x;
        int s = 0;
        #pragma unroll
        for (int r = 0; r < NRANKS; r++) s += sc[r * NEXP + e];
        long long pos = (long long)NT * HID + 2LL * NT + e;
        if (pos < out_elems) out[pos] = (float)s;
    }
}

// -------------------------------------------------------------------------
// Persistent gather: 1184 resident blocks, grid-stride over output rows,
// 2 rows per iteration (4 front-batched float4 loads per thread).
// Offset tables staged in shared once; per-thread binary search is
// broadcast-LDS (uniform address across the warp -> conflict-free).
// -------------------------------------------------------------------------
__device__ __forceinline__ int seg_search(const int* __restrict__ s_off, int row) {
    int lo = 0, hi = NSEG - 1;
    #pragma unroll
    for (int it = 0; it < 7; it++) {
        int mid = (lo + hi + 1) >> 1;
        if (s_off[mid] <= row) lo = mid; else hi = mid - 1;
    }
    return lo;
}

__global__ __launch_bounds__(256, 8)
void moe_gather_kernel(const float4* __restrict__ tokens,
                       const float* __restrict__ scales,
                       float* __restrict__ out,
                       long long out_elems) {
    __shared__ int s_off[NSEG + 1];
    __shared__ int s_base[NSEG];
    if (threadIdx.x <= NSEG) s_off[threadIdx.x] = g_out_off[threadIdx.x];
    if (threadIdx.x < NSEG)  s_base[threadIdx.x] = g_base_in[threadIdx.x];
    __syncthreads();

    const int t = threadIdx.x;
    const long long NH = (long long)NT * HID;
    float4* __restrict__ o4 = reinterpret_cast<float4*>(out);

    for (int row = blockIdx.x * 2; row < NT; row += NBLK * 2) {
        const int r0 = row, r1 = row + 1;   // NT even, row even -> r1 < NT

        int p0 = seg_search(s_off, r0);
        int p1 = seg_search(s_off, r1);
        int src0 = s_base[p0] + (r0 - s_off[p0]);
        int src1 = s_base[p1] + (r1 - s_off[p1]);

        const float4* __restrict__ in0 = tokens + (long long)src0 * VEC;
        const float4* __restrict__ in1 = tokens + (long long)src1 * VEC;
        float4* __restrict__ o0 = o4 + (long long)r0 * VEC;
        float4* __restrict__ o1 = o4 + (long long)r1 * VEC;

        // front-batch 4 independent loads, then 4 stores
        float4 a0 = __ldcs(in0 + t);
        float4 a1 = __ldcs(in0 + t + 256);
        float4 b0 = __ldcs(in1 + t);
        float4 b1 = __ldcs(in1 + t + 256);
        __stcs(o0 + t,       a0);
        __stcs(o0 + t + 256, a1);
        __stcs(o1 + t,       b0);
        __stcs(o1 + t + 256, b1);

        if (t == 0) {
            out[NH + r0]      = scales[src0];
            out[NH + NT + r0] = (float)src0;   // idx < 2^24, exact in fp32
        }
        if (t == 32) {
            out[NH + r1]      = scales[src1];
            out[NH + NT + r1] = (float)src1;
        }
    }
}

extern "C" void kernel_launch(void* const* d_in, const int* in_sizes, int n_in,
                              void* d_out, int out_size) {
    const float* tokens = (const float*)d_in[0];
    const int*   counts = (const int*)d_in[1];   // [NRANKS, NEXP]
    const float* scales = (const float*)d_in[2];
    float* out = (float*)d_out;
    const long long out_elems = (long long)out_size;

    moe_setup_kernel<<<1, 128>>>(counts, out, out_elems);
    moe_gather_kernel<<<NBLK, 256>>>((const float4*)tokens, scales, out, out_elems);
}

// round 3
// speedup vs baseline: 1.1358x; 1.1358x over previous
#include <cuda_runtime.h>
#include <cuda_bf16.h>
#include <cstdint>

// Problem constants (fixed by the reference)
#define NT      131072
#define HID     2048
#define NRANKS  8
#define NEXP    16
#define NSEG    128            // NRANKS * NEXP
#define VEC     (HID / 4)      // 512 float4 per row

// Scratch (no device allocation allowed -> __device__ globals)
__device__ int g_base_in[NSEG];     // input-row base for each output segment
__device__ int g_out_off[NSEG + 1]; // exclusive cumsum of output segment sizes
__device__ int g_src[NT];           // per-output-row source row

// -------------------------------------------------------------------------
// Setup: segment offset tables + expert_token_num tail of output.
// counts layout: counts[r * NEXP + e], rank-major (input order).
// Output segment order: p = e * NRANKS + r (expert-major, rank-minor).
// -------------------------------------------------------------------------
__global__ void moe_setup_kernel(const int* __restrict__ counts,
                                 float* __restrict__ out,
                                 long long out_elems) {
    __shared__ int sc[NSEG];
    if (threadIdx.x < NSEG) sc[threadIdx.x] = counts[threadIdx.x];
    __syncthreads();

    if (threadIdx.x == 0) {
        int in_off[NSEG + 1];
        in_off[0] = 0;
        #pragma unroll 4
        for (int s = 0; s < NSEG; s++) in_off[s + 1] = in_off[s] + sc[s];

        int acc = 0;
        for (int p = 0; p < NSEG; p++) {
            int e = p >> 3;          // p / NRANKS
            int r = p & 7;           // p % NRANKS
            int inseg = r * NEXP + e;
            g_base_in[p] = in_off[inseg];
            g_out_off[p] = acc;
            acc += sc[inseg];
        }
        g_out_off[NSEG] = acc;       // == NT
    }
    __syncthreads();

    if (threadIdx.x < NEXP) {
        int e = threadIdx.x;
        int s = 0;
        #pragma unroll
        for (int r = 0; r < NRANKS; r++) s += sc[r * NEXP + e];
        long long pos = (long long)NT * HID + 2LL * NT + e;
        if (pos < out_elems) out[pos] = (float)s;
    }
}

// -------------------------------------------------------------------------
// Index precompute: per-output-row source row (smem search), plus the
// permuted scales and idx output sections. ~2.5 MB traffic total.
// -------------------------------------------------------------------------
__global__ __launch_bounds__(256)
void moe_index_kernel(const float* __restrict__ scales,
                      float* __restrict__ out) {
    __shared__ int s_off[NSEG + 1];
    __shared__ int s_base[NSEG];
    if (threadIdx.x <= NSEG) s_off[threadIdx.x] = g_out_off[threadIdx.x];
    if (threadIdx.x < NSEG)  s_base[threadIdx.x] = g_base_in[threadIdx.x];
    __syncthreads();

    const int row = blockIdx.x * 256 + threadIdx.x;
    if (row >= NT) return;

    int lo = 0, hi = NSEG - 1;
    #pragma unroll
    for (int it = 0; it < 7; it++) {
        int mid = (lo + hi + 1) >> 1;
        if (s_off[mid] <= row) lo = mid; else hi = mid - 1;
    }
    const int src = s_base[lo] + (row - s_off[lo]);

    g_src[row] = src;
    const long long NH = (long long)NT * HID;
    out[NH + row]      = scales[src];
    out[NH + NT + row] = (float)src;   // idx < 2^24, exact in fp32
}

// -------------------------------------------------------------------------
// Gather: one block per 2 consecutive rows. No barrier, no search:
// uniform broadcast load of the two source rows, then 4 front-batched
// float4 streaming loads + 4 streaming stores per thread (16 KB / block).
// -------------------------------------------------------------------------
__global__ __launch_bounds__(256, 8)
void moe_gather_kernel(const float4* __restrict__ tokens,
                       float4* __restrict__ out4) {
    const int r0 = blockIdx.x * 2;       // NT even -> r0+1 < NT
    const int2 src = *reinterpret_cast<const int2*>(&g_src[r0]);  // uniform, aligned

    const float4* __restrict__ in0 = tokens + (long long)src.x * VEC;
    const float4* __restrict__ in1 = tokens + (long long)src.y * VEC;
    float4* __restrict__ o0 = out4 + (long long)r0 * VEC;
    float4* __restrict__ o1 = o0 + VEC;

    const int t = threadIdx.x;
    float4 a0 = __ldcs(in0 + t);
    float4 a1 = __ldcs(in0 + t + 256);
    float4 b0 = __ldcs(in1 + t);
    float4 b1 = __ldcs(in1 + t + 256);
    __stcs(o0 + t,       a0);
    __stcs(o0 + t + 256, a1);
    __stcs(o1 + t,       b0);
    __stcs(o1 + t + 256, b1);
}

extern "C" void kernel_launch(void* const* d_in, const int* in_sizes, int n_in,
                              void* d_out, int out_size) {
    const float* tokens = (const float*)d_in[0];
    const int*   counts = (const int*)d_in[1];   // [NRANKS, NEXP]
    const float* scales = (const float*)d_in[2];
    float* out = (float*)d_out;
    const long long out_elems = (long long)out_size;

    moe_setup_kernel<<<1, 128>>>(counts, out, out_elems);
    moe_index_kernel<<<(NT + 255) / 256, 256>>>(scales, out);
    moe_gather_kernel<<<NT / 2, 256>>>((const float4*)tokens, (float4*)out);
}

// round 4
// speedup vs baseline: 1.1592x; 1.0206x over previous
#include <cuda_runtime.h>
#include <cuda_bf16.h>
#include <cstdint>

// Problem constants (fixed by the reference)
#define NT      131072
#define HID     2048
#define NRANKS  8
#define NEXP    16
#define NSEG    128            // NRANKS * NEXP
#define VEC     (HID / 4)      // 512 float4 per row

// Scratch (no device allocation allowed -> __device__ global)
__device__ int g_src[NT];      // per-output-row source row

// -------------------------------------------------------------------------
// Prep: fused setup + index. Every block redundantly computes both segment
// cumsums from counts (512 B, L2-resident) via warp-shuffle block scans,
// then each thread resolves one output row: writes g_src, permuted scale,
// idx. Block 0 also writes expert_token_num. Grid = NT/256 = 512 blocks.
//
// counts layout: counts[r * NEXP + e], rank-major (input order).
// Output segment order: p = e * NRANKS + r (expert-major, rank-minor).
// -------------------------------------------------------------------------
__global__ __launch_bounds__(256)
void moe_prep_kernel(const int* __restrict__ counts,
                     const float* __restrict__ scales,
                     float* __restrict__ out,
                     long long out_elems) {
    __shared__ int sc[NSEG];        // counts, input order
    __shared__ int s_in_off[NSEG];  // exclusive cumsum, input order
    __shared__ int s_off[NSEG + 1]; // exclusive cumsum, output order
    __shared__ int s_base[NSEG];    // input base per output segment
    __shared__ int warp_sums[8];    // [0..3]: scan1, [4..7]: scan2

    const int tid = threadIdx.x;
    if (tid < NSEG) sc[tid] = counts[tid];
    __syncthreads();

    int v1 = 0, v2 = 0, incl1 = 0, incl2 = 0;
    const int lane = tid & 31, w = tid >> 5;
    if (tid < NSEG) {
        // scan 1: input-order counts
        v1 = sc[tid];
        incl1 = v1;
        #pragma unroll
        for (int d = 1; d < 32; d <<= 1) {
            int y = __shfl_up_sync(0xffffffffu, incl1, d);
            if (lane >= d) incl1 += y;
        }
        // scan 2: output-order (permuted) counts
        const int e = tid >> 3, r = tid & 7;
        v2 = sc[r * NEXP + e];
        incl2 = v2;
        #pragma unroll
        for (int d = 1; d < 32; d <<= 1) {
            int y = __shfl_up_sync(0xffffffffu, incl2, d);
            if (lane >= d) incl2 += y;
        }
        if (lane == 31) { warp_sums[w] = incl1; warp_sums[4 + w] = incl2; }
    }
    __syncthreads();

    if (tid < NSEG) {
        int base1 = 0, base2 = 0;
        for (int i = 0; i < w; i++) { base1 += warp_sums[i]; base2 += warp_sums[4 + i]; }
        s_in_off[tid] = base1 + incl1 - v1;          // exclusive
        s_off[tid]    = base2 + incl2 - v2;          // exclusive
        if (tid == NSEG - 1) s_off[NSEG] = base2 + incl2;  // == NT
    }
    __syncthreads();

    if (tid < NSEG) {
        const int e = tid >> 3, r = tid & 7;
        s_base[tid] = s_in_off[r * NEXP + e];
    }
    __syncthreads();

    const long long NH = (long long)NT * HID;

    // expert_token_num tail (block 0 only)
    if (blockIdx.x == 0 && tid < NEXP) {
        int s = 0;
        #pragma unroll
        for (int r = 0; r < NRANKS; r++) s += sc[r * NEXP + tid];
        long long pos = NH + 2LL * NT + tid;
        if (pos < out_elems) out[pos] = (float)s;
    }

    // per-output-row resolution
    const int row = blockIdx.x * 256 + tid;          // grid sized so row < NT
    int lo = 0, hi = NSEG - 1;
    #pragma unroll
    for (int it = 0; it < 7; it++) {
        int mid = (lo + hi + 1) >> 1;
        if (s_off[mid] <= row) lo = mid; else hi = mid - 1;
    }
    const int src = s_base[lo] + (row - s_off[lo]);

    g_src[row] = src;
    out[NH + row]      = scales[src];
    out[NH + NT + row] = (float)src;   // idx < 2^24, exact in fp32
}

// -------------------------------------------------------------------------
// Gather: one block per output row (R1 topology — measured best). No
// barrier, no search, no smem: one uniform broadcast load of the source
// row, then 2 streaming float4 loads + 2 streaming stores per thread.
// -------------------------------------------------------------------------
__global__ __launch_bounds__(256, 8)
void moe_gather_kernel(const float4* __restrict__ tokens,
                       float4* __restrict__ out4) {
    const int row = blockIdx.x;
    const int src = __ldg(&g_src[row]);              // uniform, L2-resident

    const float4* __restrict__ in = tokens + (long long)src * VEC;
    float4* __restrict__ o = out4 + (long long)row * VEC;

    const int t = threadIdx.x;
    float4 a = __ldcs(in + t);
    float4 b = __ldcs(in + t + 256);
    __stcs(o + t,       a);
    __stcs(o + t + 256, b);
}

extern "C" void kernel_launch(void* const* d_in, const int* in_sizes, int n_in,
                              void* d_out, int out_size) {
    const float* tokens = (const float*)d_in[0];
    const int*   counts = (const int*)d_in[1];   // [NRANKS, NEXP]
    const float* scales = (const float*)d_in[2];
    float* out = (float*)d_out;
    const long long out_elems = (long long)out_size;

    moe_prep_kernel<<<NT / 256, 256>>>(counts, scales, out, out_elems);
    moe_gather_kernel<<<NT, 256>>>((const float4*)tokens, (float4*)out);
}